// round 7
// baseline (speedup 1.0000x reference)
#include <cuda_runtime.h>
#include <math_constants.h>

#define N_SPIKES 16384
#define N_UNITS  256
#define N_NEIGHB 128
#define RANK     5
#define NCH      64
#define NCO      12
#define N_CAND   10
#define DDIM     60
#define OUT_COLS 61
#define CAP      2048
#define CPITCH   32          // cursor stride in ints = 128B (avoid L2 atomic line collisions)
#define CSH_PITCH 68         // words; lane-l LDS.128 hits banks 4l..4l+3: conflict-free per phase
#define CSH_ROWS  64         // rows 60..63 are zero padding so lane 28..31 loads are valid

typedef unsigned long long u64;

// packed fp32x2 FMA (sm_100+): d = a*b + c elementwise on (lo,hi) pairs
#define FMA2(d_, a_, b_, c_) \
    asm("fma.rn.f32x2 %0, %1, %2, %3;" : "=l"(d_) : "l"(a_), "l"(b_), "l"(c_))

__device__ __forceinline__ float lo32(u64 v) { return __int_as_float((int)(v & 0xffffffffull)); }
__device__ __forceinline__ float hi32(u64 v) { return __int_as_float((int)(v >> 32)); }

// Precomputed tables (device globals; no runtime allocation)
__device__ __align__(16) float g_H[N_NEIGHB * N_UNITS * DDIM];  // H[nid,u,:] = Coo_inv[nid] @ nu(nid,u)
__device__ float g_LLC[N_NEIGHB * N_UNITS];                     // logprop[u] - 0.5 * nu^T C nu
__device__ int   g_cursor[N_UNITS * CPITCH];                    // 128B-strided counters
__device__ __align__(16) int2 g_rec[N_UNITS * CAP];             // packed (spike, bits(q))

// ---------------------------------------------------------------------------
// Kernel 1: per-(nid, unit-quarter) precompute of H and LLC.
// grid = 512: block b -> nid = b>>2, units [(b&3)*64, +64). 8 warps x 8 units.
// C in shared, pitch 68 / 64 rows (rows 60-63 zeroed: all LDS.128 valid and
// unconditional). Inner loop: per float4 group, 10 LDS.128 feed 32 FMA2.
// Block 0 also zeroes the bucket cursors.
// ---------------------------------------------------------------------------
__global__ void __launch_bounds__(256) k_pre(const float* __restrict__ mu,
                                             const float* __restrict__ Cinv,
                                             const int*   __restrict__ obs_ix,
                                             const float* __restrict__ logprop)
{
    __shared__ __align__(16) float Csh[CSH_ROWS * CSH_PITCH];
    __shared__ __align__(16) float nub[8][8][64];   // [warp][unit-in-batch][e]
    __shared__ int   obs[NCO];

    const int nidv = blockIdx.x >> 2;
    const int quad = blockIdx.x & 3;
    const int t    = threadIdx.x;
    const int warp = t >> 5;
    const int lane = t & 31;

    if (blockIdx.x == 0) g_cursor[t * CPITCH] = 0;   // 256 threads zero 256 counters

    if (t < NCO) obs[t] = obs_ix[nidv * NCO + t];

    // C fill with float4 copies: each row is exactly 15 float4, no row crossing.
    {
        const float4* C4 = reinterpret_cast<const float4*>(Cinv + (size_t)nidv * (DDIM * DDIM));
        for (int f = t; f < DDIM * (DDIM / 4); f += 256) {
            const int r = f / 15, c4 = f % 15;
            reinterpret_cast<float4*>(Csh + r * CSH_PITCH)[c4] = C4[f];
        }
        // zero pad rows 60..63 (first 15 float4 of each, the only part read)
        if (t < 60) {
            const int r = 60 + t / 15, c4 = t % 15;
            reinterpret_cast<float4*>(Csh + r * CSH_PITCH)[c4] = make_float4(0.f, 0.f, 0.f, 0.f);
        }
    }
    __syncthreads();

    const int d0 = lane;            // always valid (< 60)
    const int d1 = lane + 32;       // real dim only when lane < 28; rows 60-63 are zeros
    const bool has1 = (d1 < DDIM);
    const int r0 = d0 / NCO, k0 = d0 % NCO;
    const int r1 = has1 ? (d1 / NCO) : 0;
    const int k1 = has1 ? (d1 % NCO) : 0;
    const int o0 = obs[k0];
    const int o1 = obs[k1];

    const int ubase = quad * 64 + warp * 8;

    // gather nu for 8 units into shared
    #pragma unroll
    for (int j = 0; j < 8; j++) {
        const int u = ubase + j;
        nub[warp][j][d0] = mu[u * (RANK * NCH) + r0 * NCH + o0];
        if (has1)
            nub[warp][j][d1] = mu[u * (RANK * NCH) + r1 * NCH + o1];
    }
    __syncwarp();

    u64 acc0[8], acc1[8];
    #pragma unroll
    for (int j = 0; j < 8; j++) { acc0[j] = 0ull; acc1[j] = 0ull; }

    const ulonglong2* Crow0 = reinterpret_cast<const ulonglong2*>(Csh + d0 * CSH_PITCH);
    const ulonglong2* Crow1 = reinterpret_cast<const ulonglong2*>(Csh + d1 * CSH_PITCH);

    #pragma unroll 5
    for (int q = 0; q < DDIM / 4; q++) {       // one float4 group (2 e-pairs) per iter
        const ulonglong2 c0 = Crow0[q];        // LDS.128, unconditional
        const ulonglong2 c1 = Crow1[q];        // LDS.128, unconditional (zeros for d1>=60)
        ulonglong2 n[8];
        #pragma unroll
        for (int j = 0; j < 8; j++)
            n[j] = reinterpret_cast<const ulonglong2*>(nub[warp][j])[q];  // broadcast LDS.128
        #pragma unroll
        for (int j = 0; j < 8; j++) {
            FMA2(acc0[j], c0.x, n[j].x, acc0[j]);
            FMA2(acc0[j], c0.y, n[j].y, acc0[j]);
        }
        #pragma unroll
        for (int j = 0; j < 8; j++) {
            FMA2(acc1[j], c1.x, n[j].x, acc1[j]);
            FMA2(acc1[j], c1.y, n[j].y, acc1[j]);
        }
    }

    #pragma unroll
    for (int j = 0; j < 8; j++) {
        const int u = ubase + j;
        const float h0 = lo32(acc0[j]) + hi32(acc0[j]);
        const float h1 = lo32(acc1[j]) + hi32(acc1[j]);
        float* Hrow = g_H + (size_t)(nidv * N_UNITS + u) * DDIM;
        Hrow[d0] = h0;
        if (has1) Hrow[d1] = h1;
        // G = nu^T C nu = h . nu
        float part = h0 * nub[warp][j][d0]
                   + (has1 ? h1 * nub[warp][j][d1] : 0.f);
        #pragma unroll
        for (int o = 16; o; o >>= 1) part += __shfl_xor_sync(0xffffffffu, part, o);
        if (lane == 0)
            g_LLC[nidv * N_UNITS + u] = logprop[u] - 0.5f * part;
    }
}

// ---------------------------------------------------------------------------
// Kernel 2: per-spike responsibilities. One warp per spike.
// Lane l<30 owns e-pair (2l,2l+1): 1 u64 feature load + 10 u64 H loads
// (clamped index, value-masked), 10 packed FMA2 dot partials, batched
// butterfly, softmax, scatter.
// ---------------------------------------------------------------------------
__global__ void __launch_bounds__(256) k_main(const float* __restrict__ features,
                                              const int*   __restrict__ cands,
                                              const int*   __restrict__ nid,
                                              const float* __restrict__ noise_lp)
{
    const int t    = threadIdx.x;
    const int warp = t >> 5;
    const int lane = t & 31;
    const int s    = blockIdx.x * 8 + warp;
    const int li   = lane < 30 ? lane : 29;   // clamped: loads always valid+aligned

    const float nlp = __ldg(noise_lp);
    const u64* xf2 = reinterpret_cast<const u64*>(features + (size_t)s * DDIM);
    u64 x2 = __ldg(&xf2[li]);
    if (lane >= 30) x2 = 0ull;                // value mask; 0 * h == 0

    const int nidv  = __ldg(&nid[s]);
    const int pbase = nidv * N_UNITS;
    const int ucached = (lane < N_CAND) ? __ldg(&cands[s * N_CAND + lane]) : 0;
    const float llc_l = (lane < N_CAND) ? g_LLC[pbase + ucached] : 0.f;

    // issue all 10 H loads before any reduction (high MLP)
    u64 h2[N_CAND];
    #pragma unroll
    for (int c = 0; c < N_CAND; c++) {
        const int u = __shfl_sync(0xffffffffu, ucached, c);
        const u64* H2 = reinterpret_cast<const u64*>(g_H + (size_t)(pbase + u) * DDIM);
        h2[c] = __ldg(&H2[li]);
    }

    float acc[N_CAND];
    #pragma unroll
    for (int c = 0; c < N_CAND; c++) {
        u64 p2 = 0ull;
        FMA2(p2, x2, h2[c], p2);
        acc[c] = lo32(p2) + hi32(p2);
    }

    // batched butterfly: 5 stages, 10 independent values per stage
    #pragma unroll
    for (int o = 16; o; o >>= 1) {
        #pragma unroll
        for (int c = 0; c < N_CAND; c++)
            acc[c] += __shfl_xor_sync(0xffffffffu, acc[c], o);
    }

    // lane c takes acc[c] (static-index select chain; no dynamic reg indexing)
    float myp = acc[0];
    #pragma unroll
    for (int c = 1; c < N_CAND; c++)
        if (lane == c) myp = acc[c];

    float myll = -CUDART_INF_F;
    if (lane < N_CAND) myll = llc_l + myp;
    if (lane == N_CAND) myll = nlp;

    // softmax across lanes 0..10
    float mx = myll;
    #pragma unroll
    for (int o = 16; o; o >>= 1) mx = fmaxf(mx, __shfl_xor_sync(0xffffffffu, mx, o));
    const float ex = (lane <= N_CAND) ? __expf(myll - mx) : 0.f;
    float sm = ex;
    #pragma unroll
    for (int o = 16; o; o >>= 1) sm += __shfl_xor_sync(0xffffffffu, sm, o);

    if (lane < N_CAND) {
        const float qv = ex / sm;
        const int u = ucached;
        const int pos = atomicAdd(&g_cursor[u * CPITCH], 1);
        if (pos < CAP) {
            g_rec[u * CAP + pos] = make_int2(s, __float_as_int(qv));
        }
    }
}

// ---------------------------------------------------------------------------
// Kernel 3: per-unit weighted reduction. One block per unit.
// 8-wide unroll, u64 feature loads (clamped lane index), packed FMA2 accs.
// Lanes 30/31 never store their accumulators, so no masking needed.
// ---------------------------------------------------------------------------
__global__ void __launch_bounds__(256) k_reduce(const float* __restrict__ features,
                                                float* __restrict__ out)
{
    const int u    = blockIdx.x;
    const int t    = threadIdx.x;
    const int warp = t >> 5;
    const int lane = t & 31;
    const int li   = lane < 30 ? lane : 29;
    const bool act = lane < 30;

    int cnt = g_cursor[u * CPITCH];
    if (cnt > CAP) cnt = CAP;

    const int base = u * CAP;
    u64 a2 = 0ull;
    float ac = 0.f;

    for (int eb = warp * 8; eb < cnt; eb += 64) {
        // up to 8 independent records per step (uniform broadcast loads)
        int   n[8];
        float q[8];
        #pragma unroll
        for (int i = 0; i < 8; i++) {
            const bool v = (eb + i) < cnt;
            const int2 rec = v ? g_rec[base + eb + i] : make_int2(0, 0);
            n[i] = rec.x;
            q[i] = v ? __int_as_float(rec.y) : 0.f;
        }
        u64 f2[8];
        #pragma unroll
        for (int i = 0; i < 8; i++) {
            const u64* xf2 = reinterpret_cast<const u64*>(features + (size_t)n[i] * DDIM);
            f2[i] = __ldg(&xf2[li]);
        }
        #pragma unroll
        for (int i = 0; i < 8; i++) {
            const unsigned qb = (unsigned)__float_as_int(q[i]);
            const u64 q2 = ((u64)qb << 32) | qb;
            FMA2(a2, q2, f2[i], a2);
            ac += q[i];
        }
    }

    __shared__ float sh[8][OUT_COLS];
    if (act) {
        sh[warp][1 + 2 * lane] = lo32(a2);   // dim 2l   -> col 1+2l
        sh[warp][2 + 2 * lane] = hi32(a2);   // dim 2l+1 -> col 2+2l
    }
    if (lane == 0) sh[warp][0] = ac;         // count column
    __syncthreads();

    if (t < OUT_COLS) {
        float sum = 0.f;
        #pragma unroll
        for (int w2 = 0; w2 < 8; w2++) sum += sh[w2][t];
        out[u * OUT_COLS + t] = sum;
    }
}

// ---------------------------------------------------------------------------
// Input order (metadata): features, mu, Coo_inv, Coo_logdet, log_proportions,
//                         noise_log_prop, cands, nid, obs_ix
// Coo_logdet is unused (cancels in the softmax).
// ---------------------------------------------------------------------------
extern "C" void kernel_launch(void* const* d_in, const int* in_sizes, int n_in,
                              void* d_out, int out_size)
{
    const float* features  = (const float*)d_in[0];
    const float* mu        = (const float*)d_in[1];
    const float* Coo_inv   = (const float*)d_in[2];
    const float* logprop   = (const float*)d_in[4];
    const float* noise_lp  = (const float*)d_in[5];
    const int*   cands     = (const int*)d_in[6];
    const int*   nidp      = (const int*)d_in[7];
    const int*   obs_ix    = (const int*)d_in[8];
    float* out = (float*)d_out;

    k_pre<<<N_NEIGHB * 4, 256>>>(mu, Coo_inv, obs_ix, logprop);
    k_main<<<N_SPIKES / 8, 256>>>(features, cands, nidp, noise_lp);
    k_reduce<<<N_UNITS, 256>>>(features, out);
}

// round 8
// speedup vs baseline: 1.0616x; 1.0616x over previous
#include <cuda_runtime.h>
#include <math_constants.h>

#define N_SPIKES 16384
#define N_UNITS  256
#define N_NEIGHB 128
#define RANK     5
#define NCH      64
#define NCO      12
#define N_CAND   10
#define DDIM     60
#define OUT_COLS 61
#define CAP      2048
#define CPITCH   32          // cursor stride in ints = 128B (avoid L2 atomic line collisions)
#define CSH_PITCH 68         // words; lane-l LDS.128 hits banks 4l..4l+3: conflict-free per phase
#define CSH_ROWS  64         // rows 60..63 are zero padding so lane 28..31 loads are valid
#define RSPLIT   4           // k_reduce blocks per unit

typedef unsigned long long u64;

// packed fp32x2 FMA (sm_100+): d = a*b + c elementwise on (lo,hi) pairs
#define FMA2(d_, a_, b_, c_) \
    asm("fma.rn.f32x2 %0, %1, %2, %3;" : "=l"(d_) : "l"(a_), "l"(b_), "l"(c_))

__device__ __forceinline__ float lo32(u64 v) { return __int_as_float((int)(v & 0xffffffffull)); }
__device__ __forceinline__ float hi32(u64 v) { return __int_as_float((int)(v >> 32)); }

// Precomputed tables (device globals; no runtime allocation)
__device__ __align__(16) float g_H[N_NEIGHB * N_UNITS * DDIM];  // H[nid,u,:] = Coo_inv[nid] @ nu(nid,u)
__device__ float g_LLC[N_NEIGHB * N_UNITS];                     // logprop[u] - 0.5 * nu^T C nu
__device__ int   g_cursor[N_UNITS * CPITCH];                    // 128B-strided counters
__device__ __align__(16) int2 g_rec[N_UNITS * CAP];             // packed (spike, bits(q))

// ---------------------------------------------------------------------------
// Kernel 1: per-(nid, unit-quarter) precompute of H and LLC.
// grid = 512: block b -> nid = b>>2, units [(b&3)*64, +64). 8 warps; each warp
// does 8 units in TWO passes of 4 (halves live accumulator registers ->
// <=64 regs -> 4 blocks/SM). C in shared, pitch 68 / 64 zero-padded rows
// (all LDS.128 valid + unconditional). Also zeroes cursors and `out`.
// ---------------------------------------------------------------------------
__global__ void __launch_bounds__(256, 4) k_pre(const float* __restrict__ mu,
                                                const float* __restrict__ Cinv,
                                                const int*   __restrict__ obs_ix,
                                                const float* __restrict__ logprop,
                                                float* __restrict__ out)
{
    __shared__ __align__(16) float Csh[CSH_ROWS * CSH_PITCH];
    __shared__ __align__(16) float nub[8][4][64];   // [warp][unit-in-pass][e]
    __shared__ int   obs[NCO];

    const int nidv = blockIdx.x >> 2;
    const int quad = blockIdx.x & 3;
    const int t    = threadIdx.x;
    const int warp = t >> 5;
    const int lane = t & 31;

    if (blockIdx.x == 0) g_cursor[t * CPITCH] = 0;   // 256 threads zero 256 counters

    // zero the output (k_reduce accumulates into it with atomics)
    {
        const int gidx = blockIdx.x * 256 + t;
        if (gidx < N_UNITS * OUT_COLS) out[gidx] = 0.f;
    }

    if (t < NCO) obs[t] = obs_ix[nidv * NCO + t];

    // C fill with float4 copies: each row is exactly 15 float4, no row crossing.
    {
        const float4* C4 = reinterpret_cast<const float4*>(Cinv + (size_t)nidv * (DDIM * DDIM));
        for (int f = t; f < DDIM * (DDIM / 4); f += 256) {
            const int r = f / 15, c4 = f % 15;
            reinterpret_cast<float4*>(Csh + r * CSH_PITCH)[c4] = C4[f];
        }
        // zero pad rows 60..63 (first 15 float4 of each, the only part read)
        if (t < 60) {
            const int r = 60 + t / 15, c4 = t % 15;
            reinterpret_cast<float4*>(Csh + r * CSH_PITCH)[c4] = make_float4(0.f, 0.f, 0.f, 0.f);
        }
    }
    __syncthreads();

    const int d0 = lane;            // always valid (< 60)
    const int d1 = lane + 32;       // real dim only when lane < 28; rows 60-63 are zeros
    const bool has1 = (d1 < DDIM);
    const int r0 = d0 / NCO, k0 = d0 % NCO;
    const int r1 = has1 ? (d1 / NCO) : 0;
    const int k1 = has1 ? (d1 % NCO) : 0;
    const int o0 = obs[k0];
    const int o1 = obs[k1];

    const ulonglong2* Crow0 = reinterpret_cast<const ulonglong2*>(Csh + d0 * CSH_PITCH);
    const ulonglong2* Crow1 = reinterpret_cast<const ulonglong2*>(Csh + d1 * CSH_PITCH);

    for (int pass = 0; pass < 2; pass++) {
        const int ubase = quad * 64 + warp * 8 + pass * 4;

        // gather nu for 4 units into shared (warp-private region)
        #pragma unroll
        for (int j = 0; j < 4; j++) {
            const int u = ubase + j;
            nub[warp][j][d0] = mu[u * (RANK * NCH) + r0 * NCH + o0];
            if (has1)
                nub[warp][j][d1] = mu[u * (RANK * NCH) + r1 * NCH + o1];
        }
        __syncwarp();

        u64 acc0[4], acc1[4];
        #pragma unroll
        for (int j = 0; j < 4; j++) { acc0[j] = 0ull; acc1[j] = 0ull; }

        #pragma unroll 5
        for (int q = 0; q < DDIM / 4; q++) {       // one float4 group (2 e-pairs) per iter
            const ulonglong2 c0 = Crow0[q];        // LDS.128, unconditional
            const ulonglong2 c1 = Crow1[q];        // LDS.128, unconditional (zeros for d1>=60)
            ulonglong2 n[4];
            #pragma unroll
            for (int j = 0; j < 4; j++)
                n[j] = reinterpret_cast<const ulonglong2*>(nub[warp][j])[q];  // broadcast LDS.128
            #pragma unroll
            for (int j = 0; j < 4; j++) {
                FMA2(acc0[j], c0.x, n[j].x, acc0[j]);
                FMA2(acc0[j], c0.y, n[j].y, acc0[j]);
            }
            #pragma unroll
            for (int j = 0; j < 4; j++) {
                FMA2(acc1[j], c1.x, n[j].x, acc1[j]);
                FMA2(acc1[j], c1.y, n[j].y, acc1[j]);
            }
        }

        #pragma unroll
        for (int j = 0; j < 4; j++) {
            const int u = ubase + j;
            const float h0 = lo32(acc0[j]) + hi32(acc0[j]);
            const float h1 = lo32(acc1[j]) + hi32(acc1[j]);
            float* Hrow = g_H + (size_t)(nidv * N_UNITS + u) * DDIM;
            Hrow[d0] = h0;
            if (has1) Hrow[d1] = h1;
            // G = nu^T C nu = h . nu
            float part = h0 * nub[warp][j][d0]
                       + (has1 ? h1 * nub[warp][j][d1] : 0.f);
            #pragma unroll
            for (int o = 16; o; o >>= 1) part += __shfl_xor_sync(0xffffffffu, part, o);
            if (lane == 0)
                g_LLC[nidv * N_UNITS + u] = logprop[u] - 0.5f * part;
        }
        __syncwarp();
    }
}

// ---------------------------------------------------------------------------
// Kernel 2: per-spike responsibilities. One warp per spike.
// Lane l<30 owns e-pair (2l,2l+1): 1 u64 feature load + 10 u64 H loads
// (clamped index, value-masked), 10 packed FMA2 dot partials, batched
// butterfly, softmax, scatter.
// ---------------------------------------------------------------------------
__global__ void __launch_bounds__(256) k_main(const float* __restrict__ features,
                                              const int*   __restrict__ cands,
                                              const int*   __restrict__ nid,
                                              const float* __restrict__ noise_lp)
{
    const int t    = threadIdx.x;
    const int warp = t >> 5;
    const int lane = t & 31;
    const int s    = blockIdx.x * 8 + warp;
    const int li   = lane < 30 ? lane : 29;   // clamped: loads always valid+aligned

    const float nlp = __ldg(noise_lp);
    const u64* xf2 = reinterpret_cast<const u64*>(features + (size_t)s * DDIM);
    u64 x2 = __ldg(&xf2[li]);
    if (lane >= 30) x2 = 0ull;                // value mask; 0 * h == 0

    const int nidv  = __ldg(&nid[s]);
    const int pbase = nidv * N_UNITS;
    const int ucached = (lane < N_CAND) ? __ldg(&cands[s * N_CAND + lane]) : 0;
    const float llc_l = (lane < N_CAND) ? g_LLC[pbase + ucached] : 0.f;

    // issue all 10 H loads before any reduction (high MLP)
    u64 h2[N_CAND];
    #pragma unroll
    for (int c = 0; c < N_CAND; c++) {
        const int u = __shfl_sync(0xffffffffu, ucached, c);
        const u64* H2 = reinterpret_cast<const u64*>(g_H + (size_t)(pbase + u) * DDIM);
        h2[c] = __ldg(&H2[li]);
    }

    float acc[N_CAND];
    #pragma unroll
    for (int c = 0; c < N_CAND; c++) {
        u64 p2 = 0ull;
        FMA2(p2, x2, h2[c], p2);
        acc[c] = lo32(p2) + hi32(p2);
    }

    // batched butterfly: 5 stages, 10 independent values per stage
    #pragma unroll
    for (int o = 16; o; o >>= 1) {
        #pragma unroll
        for (int c = 0; c < N_CAND; c++)
            acc[c] += __shfl_xor_sync(0xffffffffu, acc[c], o);
    }

    // lane c takes acc[c] (static-index select chain; no dynamic reg indexing)
    float myp = acc[0];
    #pragma unroll
    for (int c = 1; c < N_CAND; c++)
        if (lane == c) myp = acc[c];

    float myll = -CUDART_INF_F;
    if (lane < N_CAND) myll = llc_l + myp;
    if (lane == N_CAND) myll = nlp;

    // softmax across lanes 0..10
    float mx = myll;
    #pragma unroll
    for (int o = 16; o; o >>= 1) mx = fmaxf(mx, __shfl_xor_sync(0xffffffffu, mx, o));
    const float ex = (lane <= N_CAND) ? __expf(myll - mx) : 0.f;
    float sm = ex;
    #pragma unroll
    for (int o = 16; o; o >>= 1) sm += __shfl_xor_sync(0xffffffffu, sm, o);

    if (lane < N_CAND) {
        const float qv = ex / sm;
        const int u = ucached;
        const int pos = atomicAdd(&g_cursor[u * CPITCH], 1);
        if (pos < CAP) {
            g_rec[u * CAP + pos] = make_int2(s, __float_as_int(qv));
        }
    }
}

// ---------------------------------------------------------------------------
// Kernel 3: per-unit weighted reduction, RSPLIT blocks per unit (grid 1024).
// Each block takes strided 8-record chunks; partials combined in shared, then
// atomicAdd into out (RSPLIT colliding adds per address — cheap).
// ---------------------------------------------------------------------------
__global__ void __launch_bounds__(256) k_reduce(const float* __restrict__ features,
                                                float* __restrict__ out)
{
    const int u    = blockIdx.x >> 2;         // RSPLIT == 4
    const int part = blockIdx.x & 3;
    const int t    = threadIdx.x;
    const int warp = t >> 5;
    const int lane = t & 31;
    const int li   = lane < 30 ? lane : 29;
    const bool act = lane < 30;

    int cnt = g_cursor[u * CPITCH];
    if (cnt > CAP) cnt = CAP;

    const int base = u * CAP;
    const int slot = part * 8 + warp;          // 0..31 across the 4 blocks
    u64 a2 = 0ull;
    float ac = 0.f;

    for (int eb = slot * 8; eb < cnt; eb += 32 * 8) {
        // up to 8 independent records per step (uniform broadcast loads)
        int   n[8];
        float q[8];
        #pragma unroll
        for (int i = 0; i < 8; i++) {
            const bool v = (eb + i) < cnt;
            const int2 rec = v ? g_rec[base + eb + i] : make_int2(0, 0);
            n[i] = rec.x;
            q[i] = v ? __int_as_float(rec.y) : 0.f;
        }
        u64 f2[8];
        #pragma unroll
        for (int i = 0; i < 8; i++) {
            const u64* xf2 = reinterpret_cast<const u64*>(features + (size_t)n[i] * DDIM);
            f2[i] = __ldg(&xf2[li]);
        }
        #pragma unroll
        for (int i = 0; i < 8; i++) {
            const unsigned qb = (unsigned)__float_as_int(q[i]);
            const u64 q2 = ((u64)qb << 32) | qb;
            FMA2(a2, q2, f2[i], a2);
            ac += q[i];
        }
    }

    __shared__ float sh[8][OUT_COLS];
    if (act) {
        sh[warp][1 + 2 * lane] = lo32(a2);   // dim 2l   -> col 1+2l
        sh[warp][2 + 2 * lane] = hi32(a2);   // dim 2l+1 -> col 2+2l
    }
    if (lane == 0) sh[warp][0] = ac;         // count column
    __syncthreads();

    if (t < OUT_COLS) {
        float sum = 0.f;
        #pragma unroll
        for (int w2 = 0; w2 < 8; w2++) sum += sh[w2][t];
        atomicAdd(&out[u * OUT_COLS + t], sum);
    }
}

// ---------------------------------------------------------------------------
// Input order (metadata): features, mu, Coo_inv, Coo_logdet, log_proportions,
//                         noise_log_prop, cands, nid, obs_ix
// Coo_logdet is unused (cancels in the softmax).
// ---------------------------------------------------------------------------
extern "C" void kernel_launch(void* const* d_in, const int* in_sizes, int n_in,
                              void* d_out, int out_size)
{
    const float* features  = (const float*)d_in[0];
    const float* mu        = (const float*)d_in[1];
    const float* Coo_inv   = (const float*)d_in[2];
    const float* logprop   = (const float*)d_in[4];
    const float* noise_lp  = (const float*)d_in[5];
    const int*   cands     = (const int*)d_in[6];
    const int*   nidp      = (const int*)d_in[7];
    const int*   obs_ix    = (const int*)d_in[8];
    float* out = (float*)d_out;

    k_pre<<<N_NEIGHB * 4, 256>>>(mu, Coo_inv, obs_ix, logprop, out);
    k_main<<<N_SPIKES / 8, 256>>>(features, cands, nidp, noise_lp);
    k_reduce<<<N_UNITS * RSPLIT, 256>>>(features, out);
}